// round 6
// baseline (speedup 1.0000x reference)
#include <cuda_runtime.h>
#include <math.h>
#include <stdint.h>

#define B_ 8
#define N_ 16384
#define M_ 512
#define K_ 32
#define C_ 6
#define FPS_P 4096       // points per FPS CTA (N_/4)

// -------------------- scratch (no allocations allowed) --------------------
__device__ int    g_center_idx[B_ * M_];
__device__ float  g_centers[B_ * M_ * 3];
__device__ int    g_gidx[B_ * M_ * K_];
__device__ float4 g_xyz[B_ * N_];
// duplicated + per-lane-contiguous weights:
// wl[c*2*DOUT + lane*2*(DOUT/32) + 2*q + {0,1}] = w[c*DOUT + q*32 + lane]
__device__ __align__(16) float g_wd1[9 * 128];
__device__ __align__(16) float g_wd2[64 * 256];
__device__ __align__(16) float g_wd3[128 * 512];
__device__ __align__(16) float g_wd4[256 * 768];

// -------------------- helpers --------------------
__device__ __forceinline__ unsigned okey(float f) {
    unsigned u = __float_as_uint(f);
    unsigned mask = (u & 0x80000000u) ? 0xFFFFFFFFu : 0x80000000u;
    return u ^ mask;
}
__device__ __forceinline__ unsigned long long ffma2(
    unsigned long long a, unsigned long long b, unsigned long long c) {
    unsigned long long d;
    asm("fma.rn.f32x2 %0, %1, %2, %3;" : "=l"(d) : "l"(a), "l"(b), "l"(c));
    return d;
}
__device__ __forceinline__ unsigned long long pack2(float lo, float hi) {
    unsigned long long d;
    asm("mov.b64 %0, {%1, %2};" : "=l"(d) : "f"(lo), "f"(hi));
    return d;
}
__device__ __forceinline__ float2 unpk(unsigned long long v) {
    float lo, hi;
    asm("mov.b64 {%0, %1}, %2;" : "=f"(lo), "=f"(hi) : "l"(v));
    return make_float2(lo, hi);
}
__device__ __forceinline__ uint32_t smem_u32(const void* p) {
    uint32_t a;
    asm("{ .reg .u64 t; cvta.to.shared.u64 t, %1; cvt.u32.u64 %0, t; }" : "=r"(a) : "l"(p));
    return a;
}
__device__ __forceinline__ uint32_t mapa_sh(uint32_t addr, uint32_t rank) {
    uint32_t r;
    asm("mapa.shared::cluster.u32 %0, %1, %2;" : "=r"(r) : "r"(addr), "r"(rank));
    return r;
}
__device__ __forceinline__ void stsc_f(uint32_t a, float v) {
    asm volatile("st.shared::cluster.f32 [%0], %1;" :: "r"(a), "f"(v) : "memory");
}
__device__ __forceinline__ void stsc_i(uint32_t a, int v) {
    asm volatile("st.shared::cluster.b32 [%0], %1;" :: "r"(a), "r"(v) : "memory");
}
__device__ __forceinline__ void cluster_sync_() {
    asm volatile("barrier.cluster.arrive.aligned;" ::: "memory");
    asm volatile("barrier.cluster.wait.aligned;" ::: "memory");
}

// -------------------- weight prep: duplicate + per-lane layout --------------------
__global__ void dup_kernel(const float* __restrict__ src, float* __restrict__ dst,
                           int total, int D) {
    int i = blockIdx.x * blockDim.x + threadIdx.x;
    if (i < total) {
        int c = i / D, j = i - c * D;
        int q = j >> 5, lane = j & 31;
        float v = src[i];
        size_t base = (size_t)c * 2 * D + lane * 2 * (D / 32) + 2 * q;
        dst[base]     = v;
        dst[base + 1] = v;
    }
}

// -------------------- pack xyz --------------------
__global__ void pack_kernel(const float* __restrict__ pts) {
    int i = blockIdx.x * blockDim.x + threadIdx.x;
    if (i < B_ * N_) {
        const float* p = pts + (size_t)i * C_;
        float x = p[0], y = p[1], z = p[2];
        g_xyz[i] = make_float4(x, y, z, x * x + y * y + z * z);
    }
}

// -------------------- FPS: 4-CTA cluster per batch, DSMEM candidate exchange ----
#define FPS_MAIL0 (3 * FPS_P + 64 + 2)
__global__ void __launch_bounds__(1024, 1) __cluster_dims__(4, 1, 1)
fps_kernel(float* centers_out) {
    extern __shared__ float fsm[];
    float* sx = fsm;
    float* sy = fsm + FPS_P;
    float* sz = fsm + 2 * FPS_P;
    float* rd = fsm + 3 * FPS_P;           // 32
    int*   ri = (int*)(rd + 32);           // 32
    float* cand_d = fsm + 3 * FPS_P + 64;  // 1
    int*   cand_i = (int*)(cand_d + 1);    // 1

    const int b = blockIdx.x >> 2;
    const uint32_t rank = blockIdx.x & 3;
    const int tid = threadIdx.x;
    const int lane = tid & 31, wid = tid >> 5;
    const uint32_t mail_bytes = smem_u32(fsm + FPS_MAIL0);

    for (int n = tid; n < FPS_P; n += 1024) {
        float4 q = g_xyz[b * N_ + rank * FPS_P + n];
        sx[n] = q.x; sy[n] = q.y; sz[n] = q.z;
    }
    float dist[4];
#pragma unroll
    for (int j = 0; j < 4; j++) dist[j] = 1e10f;
    __syncthreads();

    if (rank == 0 && tid == 0) {
        float x = sx[0], y = sy[0], z = sz[0];
        for (uint32_t r = 0; r < 4; r++) {
            uint32_t a = mapa_sh(mail_bytes + 80, r);   // buffer 1
            stsc_f(a + 32, x);
            stsc_f(a + 48, y);
            stsc_f(a + 64, z);
        }
    }
    cluster_sync_();
    int far = 0;
    float cx = fsm[FPS_MAIL0 + 20 + 8];
    float cy = fsm[FPS_MAIL0 + 20 + 12];
    float cz = fsm[FPS_MAIL0 + 20 + 16];

    for (int it = 0; it < M_; ++it) {
        if (rank == 0 && tid == 0) {
            g_center_idx[b * M_ + it] = far;
            float* gc = g_centers + (size_t)(b * M_ + it) * 3;
            gc[0] = cx; gc[1] = cy; gc[2] = cz;
            if (centers_out) {
                float* oc = centers_out + (size_t)(b * M_ + it) * 3;
                oc[0] = cx; oc[1] = cy; oc[2] = cz;
            }
        }
        float bd = -1.0f; int bi = 0x7fffffff;
#pragma unroll
        for (int j = 0; j < 4; j++) {
            int n = j * 1024 + tid;
            float dx = sx[n] - cx, dy = sy[n] - cy, dz = sz[n] - cz;
            float d = dx * dx + dy * dy + dz * dz;
            float nd = fminf(dist[j], d);
            dist[j] = nd;
            if (nd > bd) { bd = nd; bi = n; }
        }
#pragma unroll
        for (int off = 16; off; off >>= 1) {
            float od = __shfl_down_sync(0xffffffffu, bd, off);
            int   oi = __shfl_down_sync(0xffffffffu, bi, off);
            if (od > bd || (od == bd && oi < bi)) { bd = od; bi = oi; }
        }
        if (lane == 0) { rd[wid] = bd; ri[wid] = bi; }
        __syncthreads();
        if (wid == 0) {
            float vb = rd[lane]; int vi = ri[lane];
#pragma unroll
            for (int off = 16; off; off >>= 1) {
                float od = __shfl_down_sync(0xffffffffu, vb, off);
                int   oi = __shfl_down_sync(0xffffffffu, vi, off);
                if (od > vb || (od == vb && oi < vi)) { vb = od; vi = oi; }
            }
            if (lane == 0) { *cand_d = vb; *cand_i = vi; }
        }
        __syncthreads();
        const int p = it & 1;
        if (tid == 0) {
            float d = *cand_d;
            int li = *cand_i;
            int gi = (int)rank * FPS_P + li;
            float x = sx[li], y = sy[li], z = sz[li];
            for (uint32_t r = 0; r < 4; r++) {
                uint32_t a = mapa_sh(mail_bytes + p * 80 + rank * 4, r);
                stsc_f(a, d);
                stsc_i(a + 16, gi);
                stsc_f(a + 32, x);
                stsc_f(a + 48, y);
                stsc_f(a + 64, z);
            }
        }
        cluster_sync_();
        const float* md = fsm + FPS_MAIL0 + p * 20;
        const int*   mi = (const int*)(md + 4);
        float wd = md[0]; int wi = mi[0]; int ws = 0;
#pragma unroll
        for (int s = 1; s < 4; s++) {
            float d = md[s]; int i = mi[s];
            if (d > wd || (d == wd && i < wi)) { wd = d; wi = i; ws = s; }
        }
        far = wi;
        cx = md[8 + ws]; cy = md[12 + ws]; cz = md[16 + ws];
    }
}

// -------------------- kNN: fused d2+hist, single-level select --------------------
// smem: d2s[N_] | hist/cand[2048] | scansm[256] | ctrs[8]
__global__ void __launch_bounds__(256) knn_kernel() {
    extern __shared__ float ksm[];
    float* d2s  = ksm;                       // N_
    int*   hist = (int*)(ksm + N_);          // 2048 (reused as candidate list)
    int*   scansm = hist + 2048;             // 256
    int*   ctrs = scansm + 256;              // [0]=less,[1]=cand,[2]=bin,[3]=need

    const int bid = blockIdx.x;
    const int b = bid >> 9;
    const int tid = threadIdx.x;

    float cx = g_centers[bid * 3 + 0];
    float cy = g_centers[bid * 3 + 1];
    float cz = g_centers[bid * 3 + 2];
    float cc2 = cx * cx + cy * cy + cz * cz;

    for (int i = tid; i < 2048; i += 256) hist[i] = 0;
    if (tid == 0) { ctrs[0] = 0; ctrs[1] = 0; }
    __syncthreads();

    // pass 1: d2 + histogram on top 11 bits of ordered key
    for (int n = tid; n < N_; n += 256) {
        float4 q = g_xyz[b * N_ + n];
        float dot = cx * q.x + cy * q.y + cz * q.z;
        float d2 = cc2 - 2.0f * dot + q.w;
        d2s[n] = d2;
        atomicAdd(&hist[okey(d2) >> 21], 1);
    }
    __syncthreads();

    // scan 2048 bins (8 per thread)
    int s = 0;
#pragma unroll
    for (int t = 0; t < 8; ++t) s += hist[tid * 8 + t];
    scansm[tid] = s;
    __syncthreads();
    for (int off = 1; off < 256; off <<= 1) {
        int v = (tid >= off) ? scansm[tid - off] : 0;
        __syncthreads();
        scansm[tid] += v;
        __syncthreads();
    }
    int excl = scansm[tid] - s;
    if (excl < K_ && excl + s >= K_) {
        int cum = excl;
#pragma unroll
        for (int t = 0; t < 8; ++t) {
            int c = hist[tid * 8 + t];
            if (cum + c >= K_) { ctrs[2] = tid * 8 + t; ctrs[3] = K_ - cum; break; }
            cum += c;
        }
    }
    __syncthreads();
    const unsigned selbin = (unsigned)ctrs[2];
    const int need = ctrs[3];
    __syncthreads();   // everyone has selbin/need; hist now reusable

    // pass 2: collect (order among the 32 is irrelevant downstream: max-pool)
    int* gout = g_gidx + (size_t)bid * K_;
    for (int n = tid; n < N_; n += 256) {
        unsigned bin = okey(d2s[n]) >> 21;
        if (bin < selbin) {
            int p = atomicAdd(&ctrs[0], 1);
            gout[p] = n;
        } else if (bin == selbin) {
            int e = atomicAdd(&ctrs[1], 1);
            if (e < 2048) hist[e] = n;
        }
    }
    __syncthreads();
    const int less = ctrs[0];
    const int cnt = ctrs[1];
    if (cnt <= 2048) {
        // exact (key, idx) rank selection among candidates
        for (int i = tid; i < cnt; i += 256) {
            int ni = hist[i];
            unsigned ui = okey(d2s[ni]);
            int rank = 0;
            for (int j = 0; j < cnt; ++j) {
                int nj = hist[j];
                unsigned uj = okey(d2s[nj]);
                rank += (uj < ui || (uj == ui && nj < ni)) ? 1 : 0;
            }
            if (rank < need) gout[less + rank] = ni;
        }
    } else if (tid == 0) {
        // pathological fallback: ascending-index scan of the boundary bin
        int c = 0;
        for (int n = 0; n < N_ && c < need; ++n)
            if ((okey(d2s[n]) >> 21) == selbin) { gout[less + c] = n; ++c; }
    }
}

// -------------------- fused encoder (f32x2, 128-bit LDS/LDG) ----------
// 256 threads, 8 warps; warp w owns rows 8w..8w+7 as 4 f32x2 row-pairs.
// Activations transposed in SMEM: act[c*68 + r] (16B-aligned rows).
#define AST 68

template<int CIN, int DOUT, int JT>
__device__ __forceinline__ void enc_pass(
    const float* __restrict__ in, float* __restrict__ out,
    const float* __restrict__ wl, int colbase,
    const float* __restrict__ bias,
    const float* __restrict__ gg, const float* __restrict__ bb,
    const float* __restrict__ mm, const float* __restrict__ vv,
    int warp, int lane)
{
    unsigned long long acc[4][JT];
#pragma unroll
    for (int p = 0; p < 4; p++)
#pragma unroll
        for (int j = 0; j < JT; j++) acc[p][j] = 0ull;
    const int rbase = warp * 8;
    const float* wbase = wl + lane * 2 * (DOUT / 32) + colbase / 16;
#pragma unroll 4
    for (int c = 0; c < CIN; ++c) {
        const float* inc = in + c * AST + rbase;
        ulonglong2 A0 = *(const ulonglong2*)(inc + 0);
        ulonglong2 A1 = *(const ulonglong2*)(inc + 4);
        const ulonglong2* wc = (const ulonglong2*)(wbase + (size_t)c * 2 * DOUT);
#pragma unroll
        for (int jj = 0; jj < JT / 2; ++jj) {
            ulonglong2 W = __ldg(wc + jj);
            acc[0][2*jj]   = ffma2(A0.x, W.x, acc[0][2*jj]);
            acc[1][2*jj]   = ffma2(A0.y, W.x, acc[1][2*jj]);
            acc[2][2*jj]   = ffma2(A1.x, W.x, acc[2][2*jj]);
            acc[3][2*jj]   = ffma2(A1.y, W.x, acc[3][2*jj]);
            acc[0][2*jj+1] = ffma2(A0.x, W.y, acc[0][2*jj+1]);
            acc[1][2*jj+1] = ffma2(A0.y, W.y, acc[1][2*jj+1]);
            acc[2][2*jj+1] = ffma2(A1.x, W.y, acc[2][2*jj+1]);
            acc[3][2*jj+1] = ffma2(A1.y, W.y, acc[3][2*jj+1]);
        }
    }
#pragma unroll
    for (int j = 0; j < JT; j++) {
        int col = colbase + lane + 32 * j;
        float bj  = __ldg(bias + col);
        float sc  = __ldg(gg + col) * rsqrtf(__ldg(vv + col) + 1e-5f);
        float mj  = __ldg(mm + col);
        float bet = __ldg(bb + col);
        float* op = out + col * AST + rbase;
#pragma unroll
        for (int p = 0; p < 4; p++) {
            float2 v = unpk(acc[p][j]);
            float lo = fmaxf((v.x + bj - mj) * sc + bet, 0.0f);
            float hi = fmaxf((v.y + bj - mj) * sc + bet, 0.0f);
            *(unsigned long long*)(op + 2 * p) = pack2(lo, hi);
        }
    }
}

template<int CIN, int JT>
__device__ __forceinline__ void enc_l4(
    const float* __restrict__ in, const float* __restrict__ wl, int colbase,
    const float* __restrict__ bias, float* __restrict__ maxb,
    int warp, int lane)
{
    unsigned long long acc[4][JT];
#pragma unroll
    for (int p = 0; p < 4; p++)
#pragma unroll
        for (int j = 0; j < JT; j++) acc[p][j] = 0ull;
    const int rbase = warp * 8;
    const float* wbase = wl + lane * 2 * (384 / 32) + colbase / 16;
#pragma unroll 4
    for (int c = 0; c < CIN; ++c) {
        const float* inc = in + c * AST + rbase;
        ulonglong2 A0 = *(const ulonglong2*)(inc + 0);
        ulonglong2 A1 = *(const ulonglong2*)(inc + 4);
        const ulonglong2* wc = (const ulonglong2*)(wbase + (size_t)c * 2 * 384);
#pragma unroll
        for (int jj = 0; jj < JT / 2; ++jj) {
            ulonglong2 W = __ldg(wc + jj);
            acc[0][2*jj]   = ffma2(A0.x, W.x, acc[0][2*jj]);
            acc[1][2*jj]   = ffma2(A0.y, W.x, acc[1][2*jj]);
            acc[2][2*jj]   = ffma2(A1.x, W.x, acc[2][2*jj]);
            acc[3][2*jj]   = ffma2(A1.y, W.x, acc[3][2*jj]);
            acc[0][2*jj+1] = ffma2(A0.x, W.y, acc[0][2*jj+1]);
            acc[1][2*jj+1] = ffma2(A0.y, W.y, acc[1][2*jj+1]);
            acc[2][2*jj+1] = ffma2(A1.x, W.y, acc[2][2*jj+1]);
            acc[3][2*jj+1] = ffma2(A1.y, W.y, acc[3][2*jj+1]);
        }
    }
#pragma unroll
    for (int j = 0; j < JT; j++) {
        int col = colbase + lane + 32 * j;
        float mx = -1e30f;
#pragma unroll
        for (int p = 0; p < 4; p++) {
            float2 v = unpk(acc[p][j]);
            mx = fmaxf(mx, fmaxf(v.x, v.y));
        }
        maxb[warp * 384 + col] = mx + __ldg(bias + col);
    }
}

// SMEM floats: buf0 @0 (9*68=612), bufA @612 (256*68=17408), bufB @18020 (128*68=8704)
// maxb aliases bufB during layer 4 (needs 8*384=3072 <= 8704).
__global__ void __launch_bounds__(256, 2) encoder_kernel(
    const float* __restrict__ pts,
    const float* __restrict__ b1,
    const float* __restrict__ g1, const float* __restrict__ be1,
    const float* __restrict__ m1, const float* __restrict__ v1,
    const float* __restrict__ b2,
    const float* __restrict__ g2, const float* __restrict__ be2,
    const float* __restrict__ m2, const float* __restrict__ v2,
    const float* __restrict__ b3,
    const float* __restrict__ g3, const float* __restrict__ be3,
    const float* __restrict__ m3, const float* __restrict__ v3,
    const float* __restrict__ b4,
    float* __restrict__ tokens)
{
    extern __shared__ float esm[];
    float* buf0 = esm;
    float* bufA = esm + 612;
    float* bufB = esm + 612 + 17408;
    float* maxb = bufB;                       // alias (bufB dead during L4)

    const int tid = threadIdx.x;
    const int warp = tid >> 5, lane = tid & 31;

    if (tid < 64) {
        int gid2 = blockIdx.x * 2 + (tid >> 5);
        int b = gid2 >> 9;
        int n = g_gidx[(size_t)gid2 * K_ + (tid & 31)];
        const float* p = pts + (size_t)(b * N_ + n) * C_;
        float cx = g_centers[gid2 * 3 + 0];
        float cy = g_centers[gid2 * 3 + 1];
        float cz = g_centers[gid2 * 3 + 2];
        float x = p[0], y = p[1], z = p[2];
        buf0[0 * AST + tid] = x - cx;
        buf0[1 * AST + tid] = y - cy;
        buf0[2 * AST + tid] = z - cz;
        buf0[3 * AST + tid] = x;
        buf0[4 * AST + tid] = y;
        buf0[5 * AST + tid] = z;
        buf0[6 * AST + tid] = p[3];
        buf0[7 * AST + tid] = p[4];
        buf0[8 * AST + tid] = p[5];
    }
    __syncthreads();
    enc_pass<9, 64, 2>(buf0, bufA, g_wd1, 0, b1, g1, be1, m1, v1, warp, lane);
    __syncthreads();
    enc_pass<64, 128, 4>(bufA, bufB, g_wd2, 0, b2, g2, be2, m2, v2, warp, lane);
    __syncthreads();
    enc_pass<128, 256, 4>(bufB, bufA, g_wd3, 0,   b3, g3, be3, m3, v3, warp, lane);
    enc_pass<128, 256, 4>(bufB, bufA, g_wd3, 128, b3, g3, be3, m3, v3, warp, lane);
    __syncthreads();
    enc_l4<256, 6>(bufA, g_wd4, 0,   b4, maxb, warp, lane);
    enc_l4<256, 6>(bufA, g_wd4, 192, b4, maxb, warp, lane);
    __syncthreads();
    for (int i = tid; i < 768; i += 256) {
        int g = i / 384, col = i - g * 384;
        float mx = maxb[(4 * g) * 384 + col];
#pragma unroll
        for (int w = 1; w < 4; ++w) mx = fmaxf(mx, maxb[(4 * g + w) * 384 + col]);
        tokens[(size_t)(blockIdx.x * 2 + g) * 384 + col] = mx;
    }
}

// -------------------- positional MLP (exact gelu) --------------------
__global__ void __launch_bounds__(128) pos_kernel(
    const float* __restrict__ pw1, const float* __restrict__ pb1,
    const float* __restrict__ pw2, const float* __restrict__ pb2,
    float* __restrict__ tokens)
{
    __shared__ float h[128];
    const int gid = blockIdx.x;
    const int tid = threadIdx.x;
    float cx = g_centers[gid * 3 + 0];
    float cy = g_centers[gid * 3 + 1];
    float cz = g_centers[gid * 3 + 2];
    float t = cx * __ldg(pw1 + tid) + cy * __ldg(pw1 + 128 + tid)
            + cz * __ldg(pw1 + 256 + tid) + __ldg(pb1 + tid);
    float ge = 0.5f * t * (1.0f + erff(t * 0.70710678118654752f));
    h[tid] = ge;
    __syncthreads();
#pragma unroll
    for (int jj = 0; jj < 3; ++jj) {
        int col = tid + jj * 128;
        float acc = __ldg(pb2 + col);
#pragma unroll 4
        for (int c = 0; c < 128; ++c)
            acc = fmaf(h[c], __ldg(pw2 + (size_t)c * 384 + col), acc);
        tokens[(size_t)gid * 384 + col] += acc;
    }
}

// -------------------- launch --------------------
extern "C" void kernel_launch(void* const* d_in, const int* in_sizes, int n_in,
                              void* d_out, int out_size)
{
    const float* pts = (const float*)d_in[0];
    const float* w1 = (const float*)d_in[1],  *b1 = (const float*)d_in[2];
    const float* g1 = (const float*)d_in[3],  *be1 = (const float*)d_in[4];
    const float* m1 = (const float*)d_in[5],  *v1 = (const float*)d_in[6];
    const float* w2 = (const float*)d_in[7],  *b2 = (const float*)d_in[8];
    const float* g2 = (const float*)d_in[9],  *be2 = (const float*)d_in[10];
    const float* m2 = (const float*)d_in[11], *v2 = (const float*)d_in[12];
    const float* w3 = (const float*)d_in[13], *b3 = (const float*)d_in[14];
    const float* g3 = (const float*)d_in[15], *be3 = (const float*)d_in[16];
    const float* m3 = (const float*)d_in[17], *v3 = (const float*)d_in[18];
    const float* w4 = (const float*)d_in[19], *b4 = (const float*)d_in[20];
    const float* pw1 = (const float*)d_in[21], *pb1 = (const float*)d_in[22];
    const float* pw2 = (const float*)d_in[23], *pb2 = (const float*)d_in[24];

    float* out = (float*)d_out;
    float* tokens = out;
    float* centers_out =
        (out_size >= B_ * M_ * 384 + B_ * M_ * 3) ? (out + (size_t)B_ * M_ * 384)
                                                  : nullptr;

    const int FPS_SMEM = (3 * FPS_P + 64 + 2 + 40) * 4;
    const int KNN_SMEM = (N_ + 2048 + 256 + 8) * 4;            // 74,784 B
    const int ENC_SMEM = (612 + 17408 + 8704) * 4;             // 106,896 B

    cudaFuncSetAttribute(fps_kernel, cudaFuncAttributeMaxDynamicSharedMemorySize, FPS_SMEM);
    cudaFuncSetAttribute(knn_kernel, cudaFuncAttributeMaxDynamicSharedMemorySize, KNN_SMEM);
    cudaFuncSetAttribute(encoder_kernel, cudaFuncAttributeMaxDynamicSharedMemorySize, ENC_SMEM);

    float* wd1; cudaGetSymbolAddress((void**)&wd1, g_wd1);
    float* wd2; cudaGetSymbolAddress((void**)&wd2, g_wd2);
    float* wd3; cudaGetSymbolAddress((void**)&wd3, g_wd3);
    float* wd4; cudaGetSymbolAddress((void**)&wd4, g_wd4);
    dup_kernel<<<(9 * 64 + 255) / 256, 256>>>(w1, wd1, 9 * 64, 64);
    dup_kernel<<<(64 * 128 + 255) / 256, 256>>>(w2, wd2, 64 * 128, 128);
    dup_kernel<<<(128 * 256 + 255) / 256, 256>>>(w3, wd3, 128 * 256, 256);
    dup_kernel<<<(256 * 384 + 255) / 256, 256>>>(w4, wd4, 256 * 384, 384);

    pack_kernel<<<(B_ * N_ + 255) / 256, 256>>>(pts);
    fps_kernel<<<B_ * 4, 1024, FPS_SMEM>>>(centers_out);
    knn_kernel<<<B_ * M_, 256, KNN_SMEM>>>();
    encoder_kernel<<<B_ * M_ / 2, 256, ENC_SMEM>>>(
        pts, b1, g1, be1, m1, v1, b2, g2, be2, m2, v2,
        b3, g3, be3, m3, v3, b4, tokens);
    pos_kernel<<<B_ * M_, 128>>>(pw1, pb1, pw2, pb2, tokens);
}

// round 7
// speedup vs baseline: 2.3615x; 2.3615x over previous
#include <cuda_runtime.h>
#include <math.h>
#include <stdint.h>

#define B_ 8
#define N_ 16384
#define M_ 512
#define K_ 32
#define C_ 6
#define FPS_P 4096

// -------------------- scratch --------------------
__device__ int    g_center_idx[B_ * M_];
__device__ float  g_centers[B_ * M_ * 3];
__device__ int    g_gidx[B_ * M_ * K_];
__device__ float4 g_xyz[B_ * N_];
// mma B-fragments (tf32 bits), layout [kt][ntpair][lane][4]
__device__ __align__(16) uint32_t g_wf1[2 * 4 * 128];
__device__ __align__(16) uint32_t g_wf2[8 * 8 * 128];
__device__ __align__(16) uint32_t g_wf3[16 * 16 * 128];
__device__ __align__(16) uint32_t g_wf4[32 * 24 * 128];
__device__ float g_ps[448], g_po[448];   // fused BN scale/offset (L1:0,L2:64,L3:192)

// -------------------- helpers --------------------
__device__ __forceinline__ unsigned okey(float f) {
    unsigned u = __float_as_uint(f);
    unsigned mask = (u & 0x80000000u) ? 0xFFFFFFFFu : 0x80000000u;
    return u ^ mask;
}
__device__ __forceinline__ uint32_t f2tf32(float x) {
    uint32_t r;
    asm("cvt.rna.tf32.f32 %0, %1;" : "=r"(r) : "f"(x));
    return r;
}
__device__ __forceinline__ void mma_tf32(float* c, uint32_t a0, uint32_t a1,
                                         uint32_t a2, uint32_t a3,
                                         uint32_t b0, uint32_t b1) {
    asm volatile(
        "mma.sync.aligned.m16n8k8.row.col.f32.tf32.tf32.f32 "
        "{%0,%1,%2,%3}, {%4,%5,%6,%7}, {%8,%9}, {%0,%1,%2,%3};"
        : "+f"(c[0]), "+f"(c[1]), "+f"(c[2]), "+f"(c[3])
        : "r"(a0), "r"(a1), "r"(a2), "r"(a3), "r"(b0), "r"(b1));
}
__device__ __forceinline__ uint32_t smem_u32(const void* p) {
    uint32_t a;
    asm("{ .reg .u64 t; cvta.to.shared.u64 t, %1; cvt.u32.u64 %0, t; }" : "=r"(a) : "l"(p));
    return a;
}
__device__ __forceinline__ uint32_t mapa_sh(uint32_t addr, uint32_t rank) {
    uint32_t r;
    asm("mapa.shared::cluster.u32 %0, %1, %2;" : "=r"(r) : "r"(addr), "r"(rank));
    return r;
}
__device__ __forceinline__ void stsc_f(uint32_t a, float v) {
    asm volatile("st.shared::cluster.f32 [%0], %1;" :: "r"(a), "f"(v) : "memory");
}
__device__ __forceinline__ void stsc_i(uint32_t a, int v) {
    asm volatile("st.shared::cluster.b32 [%0], %1;" :: "r"(a), "r"(v) : "memory");
}
__device__ __forceinline__ void cluster_sync_() {
    asm volatile("barrier.cluster.arrive.aligned;" ::: "memory");
    asm volatile("barrier.cluster.wait.aligned;" ::: "memory");
}

// -------------------- weight fragment prep --------------------
// dst[idx]: idx = ((kt*(DOUT/16)+p)*32 + lane)*4 + o*2 + r
// nt = 2p+o, n = nt*8 + lane/4, k = kt*8 + (lane&3) + 4r; zero-pad k >= CIN.
__global__ void prep_frag(const float* __restrict__ w, uint32_t* __restrict__ dst,
                          int CIN, int DOUT, int total) {
    int idx = blockIdx.x * blockDim.x + threadIdx.x;
    if (idx >= total) return;
    int r = idx & 1, o = (idx >> 1) & 1, lane = (idx >> 2) & 31;
    int rest = idx >> 7;
    int np = DOUT / 16;
    int p = rest % np, kt = rest / np;
    int nt = 2 * p + o;
    int n = nt * 8 + (lane >> 2);
    int k = kt * 8 + (lane & 3) + 4 * r;
    float v = (k < CIN) ? w[(size_t)k * DOUT + n] : 0.0f;
    dst[idx] = f2tf32(v);
}

__global__ void prep_p_kernel(const float* __restrict__ b, const float* __restrict__ g,
                              const float* __restrict__ be, const float* __restrict__ m,
                              const float* __restrict__ v, int off, int n) {
    int i = blockIdx.x * blockDim.x + threadIdx.x;
    if (i < n) {
        float sc = g[i] * rsqrtf(v[i] + 1e-5f);
        g_ps[off + i] = sc;
        g_po[off + i] = (b[i] - m[i]) * sc + be[i];
    }
}

// -------------------- pack xyz --------------------
__global__ void pack_kernel(const float* __restrict__ pts) {
    int i = blockIdx.x * blockDim.x + threadIdx.x;
    if (i < B_ * N_) {
        const float* p = pts + (size_t)i * C_;
        float x = p[0], y = p[1], z = p[2];
        g_xyz[i] = make_float4(x, y, z, x * x + y * y + z * z);
    }
}

// -------------------- FPS (4-CTA cluster per batch) --------------------
#define FPS_MAIL0 (3 * FPS_P + 64 + 2)
__global__ void __launch_bounds__(1024, 1) __cluster_dims__(4, 1, 1)
fps_kernel(float* centers_out) {
    extern __shared__ float fsm[];
    float* sx = fsm;
    float* sy = fsm + FPS_P;
    float* sz = fsm + 2 * FPS_P;
    float* rd = fsm + 3 * FPS_P;
    int*   ri = (int*)(rd + 32);
    float* cand_d = fsm + 3 * FPS_P + 64;
    int*   cand_i = (int*)(cand_d + 1);

    const int b = blockIdx.x >> 2;
    const uint32_t rank = blockIdx.x & 3;
    const int tid = threadIdx.x;
    const int lane = tid & 31, wid = tid >> 5;
    const uint32_t mail_bytes = smem_u32(fsm + FPS_MAIL0);

    for (int n = tid; n < FPS_P; n += 1024) {
        float4 q = g_xyz[b * N_ + rank * FPS_P + n];
        sx[n] = q.x; sy[n] = q.y; sz[n] = q.z;
    }
    float dist[4];
#pragma unroll
    for (int j = 0; j < 4; j++) dist[j] = 1e10f;
    __syncthreads();

    if (rank == 0 && tid == 0) {
        float x = sx[0], y = sy[0], z = sz[0];
        for (uint32_t r = 0; r < 4; r++) {
            uint32_t a = mapa_sh(mail_bytes + 80, r);
            stsc_f(a + 32, x);
            stsc_f(a + 48, y);
            stsc_f(a + 64, z);
        }
    }
    cluster_sync_();
    int far = 0;
    float cx = fsm[FPS_MAIL0 + 20 + 8];
    float cy = fsm[FPS_MAIL0 + 20 + 12];
    float cz = fsm[FPS_MAIL0 + 20 + 16];

    for (int it = 0; it < M_; ++it) {
        if (rank == 0 && tid == 0) {
            g_center_idx[b * M_ + it] = far;
            float* gc = g_centers + (size_t)(b * M_ + it) * 3;
            gc[0] = cx; gc[1] = cy; gc[2] = cz;
            if (centers_out) {
                float* oc = centers_out + (size_t)(b * M_ + it) * 3;
                oc[0] = cx; oc[1] = cy; oc[2] = cz;
            }
        }
        float bd = -1.0f; int bi = 0x7fffffff;
#pragma unroll
        for (int j = 0; j < 4; j++) {
            int n = j * 1024 + tid;
            float dx = sx[n] - cx, dy = sy[n] - cy, dz = sz[n] - cz;
            float d = dx * dx + dy * dy + dz * dz;
            float nd = fminf(dist[j], d);
            dist[j] = nd;
            if (nd > bd) { bd = nd; bi = n; }
        }
#pragma unroll
        for (int off = 16; off; off >>= 1) {
            float od = __shfl_down_sync(0xffffffffu, bd, off);
            int   oi = __shfl_down_sync(0xffffffffu, bi, off);
            if (od > bd || (od == bd && oi < bi)) { bd = od; bi = oi; }
        }
        if (lane == 0) { rd[wid] = bd; ri[wid] = bi; }
        __syncthreads();
        if (wid == 0) {
            float vb = rd[lane]; int vi = ri[lane];
#pragma unroll
            for (int off = 16; off; off >>= 1) {
                float od = __shfl_down_sync(0xffffffffu, vb, off);
                int   oi = __shfl_down_sync(0xffffffffu, vi, off);
                if (od > vb || (od == vb && oi < vi)) { vb = od; vi = oi; }
            }
            if (lane == 0) { *cand_d = vb; *cand_i = vi; }
        }
        __syncthreads();
        const int p = it & 1;
        if (tid == 0) {
            float d = *cand_d;
            int li = *cand_i;
            int gi = (int)rank * FPS_P + li;
            float x = sx[li], y = sy[li], z = sz[li];
            for (uint32_t r = 0; r < 4; r++) {
                uint32_t a = mapa_sh(mail_bytes + p * 80 + rank * 4, r);
                stsc_f(a, d);
                stsc_i(a + 16, gi);
                stsc_f(a + 32, x);
                stsc_f(a + 48, y);
                stsc_f(a + 64, z);
            }
        }
        cluster_sync_();
        const float* md = fsm + FPS_MAIL0 + p * 20;
        const int*   mi = (const int*)(md + 4);
        float wd = md[0]; int wi = mi[0]; int ws = 0;
#pragma unroll
        for (int s = 1; s < 4; s++) {
            float d = md[s]; int i = mi[s];
            if (d > wd || (d == wd && i < wi)) { wd = d; wi = i; ws = s; }
        }
        far = wi;
        cx = md[8 + ws]; cy = md[12 + ws]; cz = md[16 + ws];
    }
}

// -------------------- kNN (fused d2+hist, single-level select) --------------------
__global__ void __launch_bounds__(256) knn_kernel() {
    extern __shared__ float ksm[];
    float* d2s  = ksm;
    int*   hist = (int*)(ksm + N_);
    int*   scansm = hist + 2048;
    int*   ctrs = scansm + 256;

    const int bid = blockIdx.x;
    const int b = bid >> 9;
    const int tid = threadIdx.x;

    float cx = g_centers[bid * 3 + 0];
    float cy = g_centers[bid * 3 + 1];
    float cz = g_centers[bid * 3 + 2];
    float cc2 = cx * cx + cy * cy + cz * cz;

    for (int i = tid; i < 2048; i += 256) hist[i] = 0;
    if (tid == 0) { ctrs[0] = 0; ctrs[1] = 0; }
    __syncthreads();

    for (int n = tid; n < N_; n += 256) {
        float4 q = g_xyz[b * N_ + n];
        float dot = cx * q.x + cy * q.y + cz * q.z;
        float d2 = cc2 - 2.0f * dot + q.w;
        d2s[n] = d2;
        atomicAdd(&hist[okey(d2) >> 21], 1);
    }
    __syncthreads();

    int s = 0;
#pragma unroll
    for (int t = 0; t < 8; ++t) s += hist[tid * 8 + t];
    scansm[tid] = s;
    __syncthreads();
    for (int off = 1; off < 256; off <<= 1) {
        int v = (tid >= off) ? scansm[tid - off] : 0;
        __syncthreads();
        scansm[tid] += v;
        __syncthreads();
    }
    int excl = scansm[tid] - s;
    if (excl < K_ && excl + s >= K_) {
        int cum = excl;
#pragma unroll
        for (int t = 0; t < 8; ++t) {
            int c = hist[tid * 8 + t];
            if (cum + c >= K_) { ctrs[2] = tid * 8 + t; ctrs[3] = K_ - cum; break; }
            cum += c;
        }
    }
    __syncthreads();
    const unsigned selbin = (unsigned)ctrs[2];
    const int need = ctrs[3];
    __syncthreads();

    int* gout = g_gidx + (size_t)bid * K_;
    for (int n = tid; n < N_; n += 256) {
        unsigned bin = okey(d2s[n]) >> 21;
        if (bin < selbin) {
            int p = atomicAdd(&ctrs[0], 1);
            gout[p] = n;
        } else if (bin == selbin) {
            int e = atomicAdd(&ctrs[1], 1);
            if (e < 2048) hist[e] = n;
        }
    }
    __syncthreads();
    const int less = ctrs[0];
    const int cnt = ctrs[1];
    if (cnt <= 2048) {
        for (int i = tid; i < cnt; i += 256) {
            int ni = hist[i];
            unsigned ui = okey(d2s[ni]);
            int rank = 0;
            for (int j = 0; j < cnt; ++j) {
                int nj = hist[j];
                unsigned uj = okey(d2s[nj]);
                rank += (uj < ui || (uj == ui && nj < ni)) ? 1 : 0;
            }
            if (rank < need) gout[less + rank] = ni;
        }
    } else if (tid == 0) {
        int c = 0;
        for (int n = 0; n < N_ && c < need; ++n)
            if ((okey(d2s[n]) >> 21) == selbin) { gout[less + c] = n; ++c; }
    }
}

// -------------------- mma.sync tf32 encoder --------------------
// CTA = 64 rows (2 groups), 4 warps. Warp w owns rows 16w..16w+15 (m16 slab)
// for the whole chain -> only __syncwarp between layers.
// SMEM (u32): X[16640] @0, Y[8448] @16640. Strides all == 4 mod 32.

template<int KT, int NPH, int NPT, int SIN, int SOUT>
__device__ __forceinline__ void mma_layer_bn(
    const uint32_t* __restrict__ As, uint32_t* __restrict__ Ds,
    const uint32_t* __restrict__ wf, int p0,
    const float* __restrict__ ps, const float* __restrict__ po,
    int warp, int lane)
{
    float acc[2 * NPH][4];
#pragma unroll
    for (int t = 0; t < 2 * NPH; t++)
#pragma unroll
        for (int q = 0; q < 4; q++) acc[t][q] = 0.0f;
    const int g = lane >> 2, tig = lane & 3;
    const int row = warp * 16 + g;
#pragma unroll 2
    for (int kt = 0; kt < KT; kt++) {
        const uint32_t* ap = As + row * SIN + kt * 8 + tig;
        uint32_t a0 = ap[0], a2 = ap[4];
        uint32_t a1 = ap[8 * SIN], a3 = ap[8 * SIN + 4];
        const uint4* wp = (const uint4*)wf + ((size_t)(kt * NPT + p0)) * 32 + lane;
#pragma unroll
        for (int pp = 0; pp < NPH; pp++) {
            uint4 W = __ldg(wp + pp * 32);
            mma_tf32(acc[2 * pp],     a0, a1, a2, a3, W.x, W.y);
            mma_tf32(acc[2 * pp + 1], a0, a1, a2, a3, W.z, W.w);
        }
    }
#pragma unroll
    for (int t = 0; t < 2 * NPH; t++) {
        int j0 = (p0 * 2 + t) * 8 + 2 * tig;
        float s0 = __ldg(ps + j0), s1 = __ldg(ps + j0 + 1);
        float q0 = __ldg(po + j0), q1 = __ldg(po + j0 + 1);
        uint32_t* d0 = Ds + row * SOUT + j0;
        uint32_t* d1 = Ds + (row + 8) * SOUT + j0;
        d0[0] = f2tf32(fmaxf(fmaf(acc[t][0], s0, q0), 0.0f));
        d0[1] = f2tf32(fmaxf(fmaf(acc[t][1], s1, q1), 0.0f));
        d1[0] = f2tf32(fmaxf(fmaf(acc[t][2], s0, q0), 0.0f));
        d1[1] = f2tf32(fmaxf(fmaf(acc[t][3], s1, q1), 0.0f));
    }
}

template<int KT, int NPH, int NPT, int SIN>
__device__ __forceinline__ void mma_layer_max(
    const uint32_t* __restrict__ As, const uint32_t* __restrict__ wf, int p0,
    float* __restrict__ maxw, int warp, int lane)
{
    float acc[2 * NPH][4];
#pragma unroll
    for (int t = 0; t < 2 * NPH; t++)
#pragma unroll
        for (int q = 0; q < 4; q++) acc[t][q] = 0.0f;
    const int g = lane >> 2, tig = lane & 3;
    const int row = warp * 16 + g;
#pragma unroll 2
    for (int kt = 0; kt < KT; kt++) {
        const uint32_t* ap = As + row * SIN + kt * 8 + tig;
        uint32_t a0 = ap[0], a2 = ap[4];
        uint32_t a1 = ap[8 * SIN], a3 = ap[8 * SIN + 4];
        const uint4* wp = (const uint4*)wf + ((size_t)(kt * NPT + p0)) * 32 + lane;
#pragma unroll
        for (int pp = 0; pp < NPH; pp++) {
            uint4 W = __ldg(wp + pp * 32);
            mma_tf32(acc[2 * pp],     a0, a1, a2, a3, W.x, W.y);
            mma_tf32(acc[2 * pp + 1], a0, a1, a2, a3, W.z, W.w);
        }
    }
#pragma unroll
    for (int t = 0; t < 2 * NPH; t++) {
        int j0 = (p0 * 2 + t) * 8 + 2 * tig;
        float m0 = fmaxf(acc[t][0], acc[t][2]);
        float m1 = fmaxf(acc[t][1], acc[t][3]);
#pragma unroll
        for (int o = 4; o < 32; o <<= 1) {
            m0 = fmaxf(m0, __shfl_xor_sync(0xffffffffu, m0, o));
            m1 = fmaxf(m1, __shfl_xor_sync(0xffffffffu, m1, o));
        }
        if (g == 0) {
            maxw[warp * 392 + j0] = m0;
            maxw[warp * 392 + j0 + 1] = m1;
        }
    }
}

__global__ void __launch_bounds__(128, 2) encoder_kernel(
    const float* __restrict__ pts, const float* __restrict__ b4,
    float* __restrict__ tokens)
{
    extern __shared__ uint32_t esm[];
    uint32_t* X = esm;           // 16640 u32
    uint32_t* Y = esm + 16640;   // 8448 u32
    float* maxw = (float*)Y;     // aliases Y during L4 (Y dead then)

    const int tid = threadIdx.x;
    const int warp = tid >> 5, lane = tid & 31;

    // load inputs: 64 rows x 16 tf32 cols (9 real + 7 zero), stride 36
    if (tid < 64) {
        int gid2 = blockIdx.x * 2 + (tid >> 5);
        int b = gid2 >> 9;
        int n = g_gidx[(size_t)gid2 * K_ + (tid & 31)];
        const float* p = pts + (size_t)(b * N_ + n) * C_;
        float cx = g_centers[gid2 * 3 + 0];
        float cy = g_centers[gid2 * 3 + 1];
        float cz = g_centers[gid2 * 3 + 2];
        float x = p[0], y = p[1], z = p[2];
        uint32_t* r = Y + tid * 36;
        r[0] = f2tf32(x - cx); r[1] = f2tf32(y - cy); r[2] = f2tf32(z - cz);
        r[3] = f2tf32(x); r[4] = f2tf32(y); r[5] = f2tf32(z);
        r[6] = f2tf32(p[3]); r[7] = f2tf32(p[4]); r[8] = f2tf32(p[5]);
#pragma unroll
        for (int c = 9; c < 16; c++) r[c] = 0u;
    }
    __syncthreads();

    // L1: 16(pad) -> 64   (in Y s36, out X s68)
    mma_layer_bn<2, 4, 4, 36, 68>(Y, X, g_wf1, 0, g_ps, g_po, warp, lane);
    __syncwarp();
    // L2: 64 -> 128       (in X s68, out Y s132)
    mma_layer_bn<8, 8, 8, 68, 132>(X, Y, g_wf2, 0, g_ps + 64, g_po + 64, warp, lane);
    __syncwarp();
    // L3: 128 -> 256      (in Y s132, out X s260) two column halves
    mma_layer_bn<16, 8, 16, 132, 260>(Y, X, g_wf3, 0, g_ps + 192, g_po + 192, warp, lane);
    mma_layer_bn<16, 8, 16, 132, 260>(Y, X, g_wf3, 8, g_ps + 192, g_po + 192, warp, lane);
    __syncwarp();
    __syncthreads();   // Y about to be reused as maxw by all warps
    // L4: 256 -> 384 max-pool, two column halves
    mma_layer_max<32, 12, 24, 260>(X, g_wf4, 0,  maxw, warp, lane);
    mma_layer_max<32, 12, 24, 260>(X, g_wf4, 12, maxw, warp, lane);
    __syncthreads();

    // combine 2 warps per group, add bias, write tokens
    for (int i = tid; i < 768; i += 128) {
        int g = i / 384, col = i - g * 384;
        float mx = fmaxf(maxw[(2 * g) * 392 + col], maxw[(2 * g + 1) * 392 + col]);
        tokens[(size_t)(blockIdx.x * 2 + g) * 384 + col] = mx + __ldg(b4 + col);
    }
}

// -------------------- positional MLP (exact gelu) --------------------
__global__ void __launch_bounds__(128) pos_kernel(
    const float* __restrict__ pw1, const float* __restrict__ pb1,
    const float* __restrict__ pw2, const float* __restrict__ pb2,
    float* __restrict__ tokens)
{
    __shared__ float h[128];
    const int gid = blockIdx.x;
    const int tid = threadIdx.x;
    float cx = g_centers[gid * 3 + 0];
    float cy = g_centers[gid * 3 + 1];
    float cz = g_centers[gid * 3 + 2];
    float t = cx * __ldg(pw1 + tid) + cy * __ldg(pw1 + 128 + tid)
            + cz * __ldg(pw1 + 256 + tid) + __ldg(pb1 + tid);
    float ge = 0.5f * t * (1.0f + erff(t * 0.70710678118654752f));
    h[tid] = ge;
    __syncthreads();
#pragma unroll
    for (int jj = 0; jj < 3; ++jj) {
        int col = tid + jj * 128;
        float acc = __ldg(pb2 + col);
#pragma unroll 4
        for (int c = 0; c < 128; ++c)
            acc = fmaf(h[c], __ldg(pw2 + (size_t)c * 384 + col), acc);
        tokens[(size_t)gid * 384 + col] += acc;
    }
}

// -------------------- launch --------------------
extern "C" void kernel_launch(void* const* d_in, const int* in_sizes, int n_in,
                              void* d_out, int out_size)
{
    const float* pts = (const float*)d_in[0];
    const float* w1 = (const float*)d_in[1],  *b1 = (const float*)d_in[2];
    const float* g1 = (const float*)d_in[3],  *be1 = (const float*)d_in[4];
    const float* m1 = (const float*)d_in[5],  *v1 = (const float*)d_in[6];
    const float* w2 = (const float*)d_in[7],  *b2 = (const float*)d_in[8];
    const float* g2 = (const float*)d_in[9],  *be2 = (const float*)d_in[10];
    const float* m2 = (const float*)d_in[11], *v2 = (const float*)d_in[12];
    const float* w3 = (const float*)d_in[13], *b3 = (const float*)d_in[14];
    const float* g3 = (const float*)d_in[15], *be3 = (const float*)d_in[16];
    const float* m3 = (const float*)d_in[17], *v3 = (const float*)d_in[18];
    const float* w4 = (const float*)d_in[19], *b4 = (const float*)d_in[20];
    const float* pw1 = (const float*)d_in[21], *pb1 = (const float*)d_in[22];
    const float* pw2 = (const float*)d_in[23], *pb2 = (const float*)d_in[24];

    float* out = (float*)d_out;
    float* tokens = out;
    float* centers_out =
        (out_size >= B_ * M_ * 384 + B_ * M_ * 3) ? (out + (size_t)B_ * M_ * 384)
                                                  : nullptr;

    const int FPS_SMEM = (3 * FPS_P + 64 + 2 + 40) * 4;
    const int KNN_SMEM = (N_ + 2048 + 256 + 8) * 4;
    const int ENC_SMEM = (16640 + 8448) * 4;   // 100,352 B

    cudaFuncSetAttribute(fps_kernel, cudaFuncAttributeMaxDynamicSharedMemorySize, FPS_SMEM);
    cudaFuncSetAttribute(knn_kernel, cudaFuncAttributeMaxDynamicSharedMemorySize, KNN_SMEM);
    cudaFuncSetAttribute(encoder_kernel, cudaFuncAttributeMaxDynamicSharedMemorySize, ENC_SMEM);

    uint32_t* wf1; cudaGetSymbolAddress((void**)&wf1, g_wf1);
    uint32_t* wf2; cudaGetSymbolAddress((void**)&wf2, g_wf2);
    uint32_t* wf3; cudaGetSymbolAddress((void**)&wf3, g_wf3);
    uint32_t* wf4; cudaGetSymbolAddress((void**)&wf4, g_wf4);
    prep_frag<<<(2 * 4 * 128 + 255) / 256, 256>>>(w1, wf1, 9, 64, 2 * 4 * 128);
    prep_frag<<<(8 * 8 * 128 + 255) / 256, 256>>>(w2, wf2, 64, 128, 8 * 8 * 128);
    prep_frag<<<(16 * 16 * 128 + 255) / 256, 256>>>(w3, wf3, 128, 256, 16 * 16 * 128);
    prep_frag<<<(32 * 24 * 128 + 255) / 256, 256>>>(w4, wf4, 256, 384, 32 * 24 * 128);
    prep_p_kernel<<<1, 64>>>(b1, g1, be1, m1, v1, 0, 64);
    prep_p_kernel<<<1, 128>>>(b2, g2, be2, m2, v2, 64, 128);
    prep_p_kernel<<<1, 256>>>(b3, g3, be3, m3, v3, 192, 256);

    pack_kernel<<<(B_ * N_ + 255) / 256, 256>>>(pts);
    fps_kernel<<<B_ * 4, 1024, FPS_SMEM>>>(centers_out);
    knn_kernel<<<B_ * M_, 256, KNN_SMEM>>>();
    encoder_kernel<<<B_ * M_ / 2, 128, ENC_SMEM>>>(pts, b4, tokens);
    pos_kernel<<<B_ * M_, 128>>>(pw1, pb1, pw2, pb2, tokens);
}

// round 8
// speedup vs baseline: 2.8139x; 1.1916x over previous
#include <cuda_runtime.h>
#include <math.h>
#include <stdint.h>

#define B_ 8
#define N_ 16384
#define M_ 512
#define K_ 32
#define C_ 6
#define FPS_P 4096

// -------------------- scratch --------------------
__device__ int    g_center_idx[B_ * M_];
__device__ float  g_centers[B_ * M_ * 3];
__device__ int    g_gidx[B_ * M_ * K_];
__device__ float4 g_xyz[B_ * N_];
// mma B-fragments (tf32 bits), layout [kt][ntpair][lane][4]
__device__ __align__(16) uint32_t g_wf1[2 * 4 * 128];
__device__ __align__(16) uint32_t g_wf2[8 * 8 * 128];
__device__ __align__(16) uint32_t g_wf3[16 * 16 * 128];
__device__ __align__(16) uint32_t g_wf4[32 * 24 * 128];
__device__ float g_ps[448], g_po[448];

// -------------------- helpers --------------------
__device__ __forceinline__ unsigned okey(float f) {
    unsigned u = __float_as_uint(f);
    unsigned mask = (u & 0x80000000u) ? 0xFFFFFFFFu : 0x80000000u;
    return u ^ mask;
}
__device__ __forceinline__ uint32_t f2tf32(float x) {
    uint32_t r;
    asm("cvt.rna.tf32.f32 %0, %1;" : "=r"(r) : "f"(x));
    return r;
}
__device__ __forceinline__ void mma_tf32(float* c, uint32_t a0, uint32_t a1,
                                         uint32_t a2, uint32_t a3,
                                         uint32_t b0, uint32_t b1) {
    asm volatile(
        "mma.sync.aligned.m16n8k8.row.col.f32.tf32.tf32.f32 "
        "{%0,%1,%2,%3}, {%4,%5,%6,%7}, {%8,%9}, {%0,%1,%2,%3};"
        : "+f"(c[0]), "+f"(c[1]), "+f"(c[2]), "+f"(c[3])
        : "r"(a0), "r"(a1), "r"(a2), "r"(a3), "r"(b0), "r"(b1));
}
__device__ __forceinline__ uint32_t smem_u32(const void* p) {
    uint32_t a;
    asm("{ .reg .u64 t; cvta.to.shared.u64 t, %1; cvt.u32.u64 %0, t; }" : "=r"(a) : "l"(p));
    return a;
}
__device__ __forceinline__ uint32_t mapa_sh(uint32_t addr, uint32_t rank) {
    uint32_t r;
    asm("mapa.shared::cluster.u32 %0, %1, %2;" : "=r"(r) : "r"(addr), "r"(rank));
    return r;
}
__device__ __forceinline__ void stsc_f(uint32_t a, float v) {
    asm volatile("st.shared::cluster.f32 [%0], %1;" :: "r"(a), "f"(v) : "memory");
}
__device__ __forceinline__ void stsc_i(uint32_t a, int v) {
    asm volatile("st.shared::cluster.b32 [%0], %1;" :: "r"(a), "r"(v) : "memory");
}
__device__ __forceinline__ void cluster_sync_() {
    asm volatile("barrier.cluster.arrive.aligned;" ::: "memory");
    asm volatile("barrier.cluster.wait.aligned;" ::: "memory");
}
// identical FP sequence everywhere it's used (pass1/pass2 consistency)
__device__ __forceinline__ float dist2c(float cx, float cy, float cz, float cc2,
                                        float4 q) {
    float dot = __fmaf_rn(cx, q.x, __fmaf_rn(cy, q.y, __fmul_rn(cz, q.z)));
    return __fadd_rn(__fmaf_rn(-2.0f, dot, cc2), q.w);
}

// -------------------- weight fragment prep --------------------
__global__ void prep_frag(const float* __restrict__ w, uint32_t* __restrict__ dst,
                          int CIN, int DOUT, int total) {
    int idx = blockIdx.x * blockDim.x + threadIdx.x;
    if (idx >= total) return;
    int r = idx & 1, o = (idx >> 1) & 1, lane = (idx >> 2) & 31;
    int rest = idx >> 7;
    int np = DOUT / 16;
    int p = rest % np, kt = rest / np;
    int nt = 2 * p + o;
    int n = nt * 8 + (lane >> 2);
    int k = kt * 8 + (lane & 3) + 4 * r;
    float v = (k < CIN) ? w[(size_t)k * DOUT + n] : 0.0f;
    dst[idx] = f2tf32(v);
}

__global__ void prep_p_kernel(const float* __restrict__ b, const float* __restrict__ g,
                              const float* __restrict__ be, const float* __restrict__ m,
                              const float* __restrict__ v, int off, int n) {
    int i = blockIdx.x * blockDim.x + threadIdx.x;
    if (i < n) {
        float sc = g[i] * rsqrtf(v[i] + 1e-5f);
        g_ps[off + i] = sc;
        g_po[off + i] = (b[i] - m[i]) * sc + be[i];
    }
}

// -------------------- pack xyz --------------------
__global__ void pack_kernel(const float* __restrict__ pts) {
    int i = blockIdx.x * blockDim.x + threadIdx.x;
    if (i < B_ * N_) {
        const float* p = pts + (size_t)i * C_;
        float x = p[0], y = p[1], z = p[2];
        g_xyz[i] = make_float4(x, y, z, x * x + y * y + z * z);
    }
}

// -------------------- FPS (4-CTA cluster, redux.sync reduces) --------------------
#define FPS_MAIL0 (3 * FPS_P + 64 + 2)
__global__ void __launch_bounds__(1024, 1) __cluster_dims__(4, 1, 1)
fps_kernel(float* centers_out) {
    extern __shared__ float fsm[];
    float* sx = fsm;
    float* sy = fsm + FPS_P;
    float* sz = fsm + 2 * FPS_P;
    unsigned* rk = (unsigned*)(fsm + 3 * FPS_P);   // 32
    unsigned* ri = (unsigned*)(rk + 32);           // 32
    unsigned* cand_k = (unsigned*)(fsm + 3 * FPS_P + 64);  // 1
    int*      cand_i = (int*)(cand_k + 1);                 // 1

    const int b = blockIdx.x >> 2;
    const uint32_t rank = blockIdx.x & 3;
    const int tid = threadIdx.x;
    const int lane = tid & 31, wid = tid >> 5;
    const uint32_t mail_bytes = smem_u32(fsm + FPS_MAIL0);

    for (int n = tid; n < FPS_P; n += 1024) {
        float4 q = g_xyz[b * N_ + rank * FPS_P + n];
        sx[n] = q.x; sy[n] = q.y; sz[n] = q.z;
    }
    float dist[4];
#pragma unroll
    for (int j = 0; j < 4; j++) dist[j] = 1e10f;
    __syncthreads();

    if (rank == 0 && tid == 0) {
        float x = sx[0], y = sy[0], z = sz[0];
        for (uint32_t r = 0; r < 4; r++) {
            uint32_t a = mapa_sh(mail_bytes + 80, r);
            stsc_f(a + 32, x);
            stsc_f(a + 48, y);
            stsc_f(a + 64, z);
        }
    }
    cluster_sync_();
    int far = 0;
    float cx = fsm[FPS_MAIL0 + 20 + 8];
    float cy = fsm[FPS_MAIL0 + 20 + 12];
    float cz = fsm[FPS_MAIL0 + 20 + 16];

    for (int it = 0; it < M_; ++it) {
        if (rank == 0 && tid == 0) {
            g_center_idx[b * M_ + it] = far;
            float* gc = g_centers + (size_t)(b * M_ + it) * 3;
            gc[0] = cx; gc[1] = cy; gc[2] = cz;
            if (centers_out) {
                float* oc = centers_out + (size_t)(b * M_ + it) * 3;
                oc[0] = cx; oc[1] = cy; oc[2] = cz;
            }
        }
        float bd = -1.0f; int bi = 0x7fffffff;
#pragma unroll
        for (int j = 0; j < 4; j++) {
            int n = j * 1024 + tid;
            float dx = sx[n] - cx, dy = sy[n] - cy, dz = sz[n] - cz;
            float d = dx * dx + dy * dy + dz * dz;
            float nd = fminf(dist[j], d);
            dist[j] = nd;
            if (nd > bd) { bd = nd; bi = n; }
        }
        // warp reduce: max key, tie -> min index
        unsigned key = okey(bd);
        unsigned kmax = __reduce_max_sync(0xffffffffu, key);
        unsigned cnd = (key == kmax) ? (unsigned)bi : 0xffffffffu;
        unsigned imin = __reduce_min_sync(0xffffffffu, cnd);
        if (lane == 0) { rk[wid] = kmax; ri[wid] = imin; }
        __syncthreads();
        if (wid == 0) {
            unsigned k2 = rk[lane], i2 = ri[lane];
            unsigned kmax2 = __reduce_max_sync(0xffffffffu, k2);
            unsigned cnd2 = (k2 == kmax2) ? i2 : 0xffffffffu;
            unsigned imin2 = __reduce_min_sync(0xffffffffu, cnd2);
            if (lane == 0) { *cand_k = kmax2; *cand_i = (int)imin2; }
        }
        __syncthreads();
        const int p = it & 1;
        if (tid == 0) {
            unsigned k = *cand_k;
            int li = *cand_i;
            int gi = (int)rank * FPS_P + li;
            float x = sx[li], y = sy[li], z = sz[li];
            for (uint32_t r = 0; r < 4; r++) {
                uint32_t a = mapa_sh(mail_bytes + p * 80 + rank * 4, r);
                stsc_i(a, (int)k);
                stsc_i(a + 16, gi);
                stsc_f(a + 32, x);
                stsc_f(a + 48, y);
                stsc_f(a + 64, z);
            }
        }
        cluster_sync_();
        const unsigned* mk = (const unsigned*)(fsm + FPS_MAIL0 + p * 20);
        const int*      mi = (const int*)(mk + 4);
        const float*    md = (const float*)(mk + 8);
        unsigned wkey = mk[0]; int wi = mi[0]; int ws = 0;
#pragma unroll
        for (int s = 1; s < 4; s++) {
            unsigned k = mk[s]; int i = mi[s];
            if (k > wkey || (k == wkey && i < wi)) { wkey = k; wi = i; ws = s; }
        }
        far = wi;
        cx = md[ws]; cy = md[4 + ws]; cz = md[8 + ws];
    }
}

// -------------------- kNN: 4 centers/CTA, recompute-d2, single-level select ------
#define KNN_C 4
__global__ void __launch_bounds__(256) knn_kernel() {
    __shared__ int hist[KNN_C * 2048];     // 32KB; reused as cand idx[0..1023]+key[1024..2047]
    __shared__ int scansm[256];
    __shared__ int selbin[KNN_C], lessc[KNN_C], candc[KNN_C];

    const int bid = blockIdx.x;            // B_*M_/KNN_C blocks
    const int gid0 = bid * KNN_C;
    const int b = gid0 >> 9;
    const int tid = threadIdx.x;

    float cx[KNN_C], cy[KNN_C], cz[KNN_C], cc2[KNN_C];
#pragma unroll
    for (int c = 0; c < KNN_C; c++) {
        cx[c] = g_centers[(gid0 + c) * 3 + 0];
        cy[c] = g_centers[(gid0 + c) * 3 + 1];
        cz[c] = g_centers[(gid0 + c) * 3 + 2];
        cc2[c] = __fmaf_rn(cx[c], cx[c], __fmaf_rn(cy[c], cy[c], __fmul_rn(cz[c], cz[c])));
    }
    for (int i = tid; i < KNN_C * 2048; i += 256) hist[i] = 0;
    __syncthreads();

    // pass 1: histogram of top-11 key bits
    for (int n = tid; n < N_; n += 256) {
        float4 q = g_xyz[b * N_ + n];
#pragma unroll
        for (int c = 0; c < KNN_C; c++) {
            float d2 = dist2c(cx[c], cy[c], cz[c], cc2[c], q);
            atomicAdd(&hist[c * 2048 + (okey(d2) >> 21)], 1);
        }
    }
    __syncthreads();

    // per-center scan + boundary-bin find
    for (int c = 0; c < KNN_C; c++) {
        int* hc = hist + c * 2048;
        int s = 0;
#pragma unroll
        for (int t = 0; t < 8; ++t) s += hc[tid * 8 + t];
        scansm[tid] = s;
        __syncthreads();
        for (int off = 1; off < 256; off <<= 1) {
            int v = (tid >= off) ? scansm[tid - off] : 0;
            __syncthreads();
            scansm[tid] += v;
            __syncthreads();
        }
        int excl = scansm[tid] - s;
        if (excl < K_ && excl + s >= K_) {
            int cum = excl;
#pragma unroll
            for (int t = 0; t < 8; ++t) {
                int cc = hc[tid * 8 + t];
                if (cum + cc >= K_) { selbin[c] = tid * 8 + t; break; }
                cum += cc;
            }
        }
        __syncthreads();
    }
    if (tid < KNN_C) { lessc[tid] = 0; candc[tid] = 0; }
    __syncthreads();

    // pass 2: emit below-bin directly; boundary bin to candidate list (idx+key)
    for (int n = tid; n < N_; n += 256) {
        float4 q = g_xyz[b * N_ + n];
#pragma unroll
        for (int c = 0; c < KNN_C; c++) {
            float d2 = dist2c(cx[c], cy[c], cz[c], cc2[c], q);
            unsigned u = okey(d2);
            int bin = (int)(u >> 21);
            if (bin < selbin[c]) {
                int p = atomicAdd(&lessc[c], 1);
                g_gidx[(size_t)(gid0 + c) * K_ + p] = n;
            } else if (bin == selbin[c]) {
                int e = atomicAdd(&candc[c], 1);
                if (e < 1024) {
                    hist[c * 2048 + e] = n;
                    hist[c * 2048 + 1024 + e] = (int)u;
                }
            }
        }
    }
    __syncthreads();

    // per-center exact rank selection among boundary candidates
    for (int c = 0; c < KNN_C; c++) {
        int less = lessc[c];
        int cnt = candc[c];
        int need = K_ - less;
        int* gout = g_gidx + (size_t)(gid0 + c) * K_;
        if (cnt <= 1024) {
            int* cl = hist + c * 2048;
            for (int i = tid; i < cnt; i += 256) {
                int ni = cl[i];
                unsigned ui = (unsigned)cl[1024 + i];
                int rnk = 0;
                for (int j = 0; j < cnt; ++j) {
                    unsigned uj = (unsigned)cl[1024 + j];
                    int nj = cl[j];
                    rnk += (uj < ui || (uj == ui && nj < ni)) ? 1 : 0;
                }
                if (rnk < need) gout[less + rnk] = ni;
            }
        } else if (tid == 0) {
            int cc = 0;
            for (int n = 0; n < N_ && cc < need; ++n) {
                float4 q = g_xyz[b * N_ + n];
                float d2 = dist2c(cx[c], cy[c], cz[c], cc2[c], q);
                if ((int)(okey(d2) >> 21) == selbin[c]) { gout[less + cc] = n; ++cc; }
            }
        }
    }
}

// -------------------- mma.sync tf32 encoder (unchanged from R7) --------------------
template<int KT, int NPH, int NPT, int SIN, int SOUT>
__device__ __forceinline__ void mma_layer_bn(
    const uint32_t* __restrict__ As, uint32_t* __restrict__ Ds,
    const uint32_t* __restrict__ wf, int p0,
    const float* __restrict__ ps, const float* __restrict__ po,
    int warp, int lane)
{
    float acc[2 * NPH][4];
#pragma unroll
    for (int t = 0; t < 2 * NPH; t++)
#pragma unroll
        for (int q = 0; q < 4; q++) acc[t][q] = 0.0f;
    const int g = lane >> 2, tig = lane & 3;
    const int row = warp * 16 + g;
#pragma unroll 2
    for (int kt = 0; kt < KT; kt++) {
        const uint32_t* ap = As + row * SIN + kt * 8 + tig;
        uint32_t a0 = ap[0], a2 = ap[4];
        uint32_t a1 = ap[8 * SIN], a3 = ap[8 * SIN + 4];
        const uint4* wp = (const uint4*)wf + ((size_t)(kt * NPT + p0)) * 32 + lane;
#pragma unroll
        for (int pp = 0; pp < NPH; pp++) {
            uint4 W = __ldg(wp + pp * 32);
            mma_tf32(acc[2 * pp],     a0, a1, a2, a3, W.x, W.y);
            mma_tf32(acc[2 * pp + 1], a0, a1, a2, a3, W.z, W.w);
        }
    }
#pragma unroll
    for (int t = 0; t < 2 * NPH; t++) {
        int j0 = (p0 * 2 + t) * 8 + 2 * tig;
        float s0 = __ldg(ps + j0), s1 = __ldg(ps + j0 + 1);
        float q0 = __ldg(po + j0), q1 = __ldg(po + j0 + 1);
        uint32_t* d0 = Ds + row * SOUT + j0;
        uint32_t* d1 = Ds + (row + 8) * SOUT + j0;
        d0[0] = f2tf32(fmaxf(fmaf(acc[t][0], s0, q0), 0.0f));
        d0[1] = f2tf32(fmaxf(fmaf(acc[t][1], s1, q1), 0.0f));
        d1[0] = f2tf32(fmaxf(fmaf(acc[t][2], s0, q0), 0.0f));
        d1[1] = f2tf32(fmaxf(fmaf(acc[t][3], s1, q1), 0.0f));
    }
}

template<int KT, int NPH, int NPT, int SIN>
__device__ __forceinline__ void mma_layer_max(
    const uint32_t* __restrict__ As, const uint32_t* __restrict__ wf, int p0,
    float* __restrict__ maxw, int warp, int lane)
{
    float acc[2 * NPH][4];
#pragma unroll
    for (int t = 0; t < 2 * NPH; t++)
#pragma unroll
        for (int q = 0; q < 4; q++) acc[t][q] = 0.0f;
    const int g = lane >> 2, tig = lane & 3;
    const int row = warp * 16 + g;
#pragma unroll 2
    for (int kt = 0; kt < KT; kt++) {
        const uint32_t* ap = As + row * SIN + kt * 8 + tig;
        uint32_t a0 = ap[0], a2 = ap[4];
        uint32_t a1 = ap[8 * SIN], a3 = ap[8 * SIN + 4];
        const uint4* wp = (const uint4*)wf + ((size_t)(kt * NPT + p0)) * 32 + lane;
#pragma unroll
        for (int pp = 0; pp < NPH; pp++) {
            uint4 W = __ldg(wp + pp * 32);
            mma_tf32(acc[2 * pp],     a0, a1, a2, a3, W.x, W.y);
            mma_tf32(acc[2 * pp + 1], a0, a1, a2, a3, W.z, W.w);
        }
    }
#pragma unroll
    for (int t = 0; t < 2 * NPH; t++) {
        int j0 = (p0 * 2 + t) * 8 + 2 * tig;
        float m0 = fmaxf(acc[t][0], acc[t][2]);
        float m1 = fmaxf(acc[t][1], acc[t][3]);
#pragma unroll
        for (int o = 4; o < 32; o <<= 1) {
            m0 = fmaxf(m0, __shfl_xor_sync(0xffffffffu, m0, o));
            m1 = fmaxf(m1, __shfl_xor_sync(0xffffffffu, m1, o));
        }
        if (g == 0) {
            maxw[warp * 392 + j0] = m0;
            maxw[warp * 392 + j0 + 1] = m1;
        }
    }
}

__global__ void __launch_bounds__(128, 2) encoder_kernel(
    const float* __restrict__ pts, const float* __restrict__ b4,
    float* __restrict__ tokens)
{
    extern __shared__ uint32_t esm[];
    uint32_t* X = esm;
    uint32_t* Y = esm + 16640;
    float* maxw = (float*)Y;

    const int tid = threadIdx.x;
    const int warp = tid >> 5, lane = tid & 31;

    if (tid < 64) {
        int gid2 = blockIdx.x * 2 + (tid >> 5);
        int b = gid2 >> 9;
        int n = g_gidx[(size_t)gid2 * K_ + (tid & 31)];
        const float* p = pts + (size_t)(b * N_ + n) * C_;
        float cx = g_centers[gid2 * 3 + 0];
        float cy = g_centers[gid2 * 3 + 1];
        float cz = g_centers[gid2 * 3 + 2];
        float x = p[0], y = p[1], z = p[2];
        uint32_t* r = Y + tid * 36;
        r[0] = f2tf32(x - cx); r[1] = f2tf32(y - cy); r[2] = f2tf32(z - cz);
        r[3] = f2tf32(x); r[4] = f2tf32(y); r[5] = f2tf32(z);
        r[6] = f2tf32(p[3]); r[7] = f2tf32(p[4]); r[8] = f2tf32(p[5]);
#pragma unroll
        for (int c = 9; c < 16; c++) r[c] = 0u;
    }
    __syncthreads();

    mma_layer_bn<2, 4, 4, 36, 68>(Y, X, g_wf1, 0, g_ps, g_po, warp, lane);
    __syncwarp();
    mma_layer_bn<8, 8, 8, 68, 132>(X, Y, g_wf2, 0, g_ps + 64, g_po + 64, warp, lane);
    __syncwarp();
    mma_layer_bn<16, 8, 16, 132, 260>(Y, X, g_wf3, 0, g_ps + 192, g_po + 192, warp, lane);
    mma_layer_bn<16, 8, 16, 132, 260>(Y, X, g_wf3, 8, g_ps + 192, g_po + 192, warp, lane);
    __syncwarp();
    __syncthreads();
    mma_layer_max<32, 12, 24, 260>(X, g_wf4, 0,  maxw, warp, lane);
    mma_layer_max<32, 12, 24, 260>(X, g_wf4, 12, maxw, warp, lane);
    __syncthreads();

    for (int i = tid; i < 768; i += 128) {
        int g = i / 384, col = i - g * 384;
        float mx = fmaxf(maxw[(2 * g) * 392 + col], maxw[(2 * g + 1) * 392 + col]);
        tokens[(size_t)(blockIdx.x * 2 + g) * 384 + col] = mx + __ldg(b4 + col);
    }
}

// -------------------- positional MLP: 8 centers/CTA --------------------
__global__ void __launch_bounds__(384) pos_kernel(
    const float* __restrict__ pw1, const float* __restrict__ pb1,
    const float* __restrict__ pw2, const float* __restrict__ pb2,
    float* __restrict__ tokens)
{
    __shared__ float h[8 * 128];
    const int gid0 = blockIdx.x * 8;
    const int tid = threadIdx.x;

    for (int idx = tid; idx < 8 * 128; idx += 384) {
        int c = idx >> 7, col = idx & 127;
        float cx = g_centers[(gid0 + c) * 3 + 0];
        float cy = g_centers[(gid0 + c) * 3 + 1];
        float cz = g_centers[(gid0 + c) * 3 + 2];
        float t = cx * __ldg(pw1 + col) + cy * __ldg(pw1 + 128 + col)
                + cz * __ldg(pw1 + 256 + col) + __ldg(pb1 + col);
        h[idx] = 0.5f * t * (1.0f + erff(t * 0.70710678118654752f));
    }
    __syncthreads();

    const int col = tid;   // 384 cols
    float acc[8];
    float bj = __ldg(pb2 + col);
#pragma unroll
    for (int c = 0; c < 8; c++) acc[c] = bj;
#pragma unroll 2
    for (int k = 0; k < 128; ++k) {
        float w = __ldg(pw2 + (size_t)k * 384 + col);
#pragma unroll
        for (int c = 0; c < 8; c++)
            acc[c] = fmaf(h[c * 128 + k], w, acc[c]);
    }
#pragma unroll
    for (int c = 0; c < 8; c++)
        tokens[(size_t)(gid0 + c) * 384 + col] += acc[c];
}

// -------------------- launch --------------------
extern "C" void kernel_launch(void* const* d_in, const int* in_sizes, int n_in,
                              void* d_out, int out_size)
{
    const float* pts = (const float*)d_in[0];
    const float* w1 = (const float*)d_in[1],  *b1 = (const float*)d_in[2];
    const float* g1 = (const float*)d_in[3],  *be1 = (const float*)d_in[4];
    const float* m1 = (const float*)d_in[5],  *v1 = (const float*)d_in[6];
    const float* w2 = (const float*)d_in[7],  *b2 = (const float*)d_in[8];
    const float* g2 = (const float*)d_in[9],  *be2 = (const float*)d_in[10];
    const float* m2 = (const float*)d_in[11], *v2 = (const float*)d_in[12];
    const float* w3 = (const float*)d_in[13], *b3 = (const float*)d_in[14];
    const float* g3 = (const float*)d_in[15], *be3 = (const float*)d_in[16];
    const float* m3 = (const float*)d_in[17], *v3 = (const float*)d_in[18];
    const float* w4 = (const float*)d_in[19], *b4 = (const float*)d_in[20];
    const float* pw1 = (const float*)d_in[21], *pb1 = (const float*)d_in[22];
    const float* pw2 = (const float*)d_in[23], *pb2 = (const float*)d_in[24];

    float* out = (float*)d_out;
    float* tokens = out;
    float* centers_out =
        (out_size >= B_ * M_ * 384 + B_ * M_ * 3) ? (out + (size_t)B_ * M_ * 384)
                                                  : nullptr;

    const int FPS_SMEM = (3 * FPS_P + 64 + 2 + 40) * 4;
    const int ENC_SMEM = (16640 + 8448) * 4;   // 100,352 B

    cudaFuncSetAttribute(fps_kernel, cudaFuncAttributeMaxDynamicSharedMemorySize, FPS_SMEM);
    cudaFuncSetAttribute(encoder_kernel, cudaFuncAttributeMaxDynamicSharedMemorySize, ENC_SMEM);

    uint32_t* wf1; cudaGetSymbolAddress((void**)&wf1, g_wf1);
    uint32_t* wf2; cudaGetSymbolAddress((void**)&wf2, g_wf2);
    uint32_t* wf3; cudaGetSymbolAddress((void**)&wf3, g_wf3);
    uint32_t* wf4; cudaGetSymbolAddress((void**)&wf4, g_wf4);
    prep_frag<<<(2 * 4 * 128 + 255) / 256, 256>>>(w1, wf1, 9, 64, 2 * 4 * 128);
    prep_frag<<<(8 * 8 * 128 + 255) / 256, 256>>>(w2, wf2, 64, 128, 8 * 8 * 128);
    prep_frag<<<(16 * 16 * 128 + 255) / 256, 256>>>(w3, wf3, 128, 256, 16 * 16 * 128);
    prep_frag<<<(32 * 24 * 128 + 255) / 256, 256>>>(w4, wf4, 256, 384, 32 * 24 * 128);
    prep_p_kernel<<<1, 64>>>(b1, g1, be1, m1, v1, 0, 64);
    prep_p_kernel<<<1, 128>>>(b2, g2, be2, m2, v2, 64, 128);
    prep_p_kernel<<<1, 256>>>(b3, g3, be3, m3, v3, 192, 256);

    pack_kernel<<<(B_ * N_ + 255) / 256, 256>>>(pts);
    fps_kernel<<<B_ * 4, 1024, FPS_SMEM>>>(centers_out);
    knn_kernel<<<B_ * M_ / KNN_C, 256>>>();
    encoder_kernel<<<B_ * M_ / 2, 128, ENC_SMEM>>>(pts, b4, tokens);
    pos_kernel<<<B_ * M_ / 8, 384>>>(pw1, pb1, pw2, pb2, tokens);
}